// round 15
// baseline (speedup 1.0000x reference)
#include <cuda_runtime.h>
#include <cuda_fp16.h>
#include <cstdint>

#define BATCH 16
#define CH    2048
#define HID   256
#define HW    1024

// ---- pre-split fp16 operand storage + fp32 scores ----
__device__ __align__(128) __half g_XqHi[BATCH*CH*HW];
__device__ __align__(128) __half g_XpHi[BATCH*CH*HW];
__device__ __align__(128) __half g_WHi [HID*CH],      g_WLo [HID*CH];
__device__ __align__(128) __half g_QHi [BATCH*HW*HID], g_QLo[BATCH*HW*HID];
__device__ __align__(128) __half g_KHi [BATCH*HW*HID], g_KLo[BATCH*HW*HID];
__device__ __align__(128) __half g_PHi [BATCH*HW*HW];
__device__ __align__(128) float  g_S   [BATCH*HW*HW];

// ===========================================================================
// Helpers (base-target sm_80+ instructions only)
// ===========================================================================
__device__ __forceinline__ uint32_t smem_u32(const void* p) {
    uint32_t a;
    asm("{ .reg .u64 t; cvta.to.shared.u64 t, %1; cvt.u32.u64 %0, t; }" : "=r"(a) : "l"(p));
    return a;
}
__device__ __forceinline__ void ldsm4(uint32_t (&r)[4], uint32_t addr) {
    asm volatile("ldmatrix.sync.aligned.m8n8.x4.shared.b16 {%0,%1,%2,%3}, [%4];"
                 : "=r"(r[0]), "=r"(r[1]), "=r"(r[2]), "=r"(r[3]) : "r"(addr));
}
__device__ __forceinline__ void ldsm4t(uint32_t (&r)[4], uint32_t addr) {
    asm volatile("ldmatrix.sync.aligned.m8n8.x4.trans.shared.b16 {%0,%1,%2,%3}, [%4];"
                 : "=r"(r[0]), "=r"(r[1]), "=r"(r[2]), "=r"(r[3]) : "r"(addr));
}
__device__ __forceinline__ void mma_f16(float (&d)[4], const uint32_t (&a)[4],
                                        uint32_t b0, uint32_t b1) {
    asm volatile("mma.sync.aligned.m16n8k16.row.col.f32.f16.f16.f32 "
                 "{%0,%1,%2,%3}, {%4,%5,%6,%7}, {%8,%9}, {%0,%1,%2,%3};"
                 : "+f"(d[0]), "+f"(d[1]), "+f"(d[2]), "+f"(d[3])
                 : "r"(a[0]), "r"(a[1]), "r"(a[2]), "r"(a[3]), "r"(b0), "r"(b1));
}
__device__ __forceinline__ void split2h(float x0, float x1, uint32_t& hi, uint32_t& lo) {
    uint32_t h;
    asm("cvt.rn.f16x2.f32 %0, %1, %2;" : "=r"(h) : "f"(x1), "f"(x0));
    __half2 hh = *reinterpret_cast<__half2*>(&h);
    float h0 = __low2float(hh), h1 = __high2float(hh);
    float l0 = x0 - h0, l1 = x1 - h1;
    uint32_t l;
    asm("cvt.rn.f16x2.f32 %0, %1, %2;" : "=r"(l) : "f"(l1), "f"(l0));
    hi = h; lo = l;
}
__device__ __forceinline__ uint32_t pack_h2(float x0, float x1) {
    uint32_t h;
    asm("cvt.rn.f16x2.f32 %0, %1, %2;" : "=r"(h) : "f"(x1), "f"(x0));
    return h;
}
__device__ __forceinline__ void cp16(uint32_t dst, const void* src) {
    asm volatile("cp.async.cg.shared.global [%0], [%1], 16;" :: "r"(dst), "l"(src));
}
#define CP_COMMIT()  asm volatile("cp.async.commit_group;" ::: "memory")

// SMEM geometry: 80B rows (32 f16 + 16B pad) and 272B trans rows are
// conflict-free for every ldmatrix phase.
#define RS     80
#define RS_T   272

// Per-TERMS SMEM layout (bytes within a stage)
template<int TERMS> struct Lay {
    static constexpr int ALO = (TERMS == 3) ? 10240 : 0;
    static constexpr int BHI = (TERMS == 3) ? 20480 : 10240;
    static constexpr int BLO = (TERMS == 3) ? 30720 : ((TERMS == 2) ? 20480 : 10240);
    static constexpr int STG = (TERMS == 3) ? 40960 : ((TERMS == 2) ? 30720 : 20480);
};

// ===========================================================================
// cp.async stage issue: A hi (+lo if TERMS==3), B hi (+lo if TERMS>=2)
// ===========================================================================
template<int TRANSA, int TERMS>
__device__ __forceinline__ void issue_stage(uint32_t sb,
        const char* Ahi, const char* Alo, const char* Bhi, const char* Blo,
        int k0, int ldA, int ldB, int tid) {
#pragma unroll
    for (int p = 0; p < 2; ++p) {
        int i = p * 256 + tid;
        uint32_t dst; size_t so;
        if (TRANSA) {
            int r = i >> 4, c = (i & 15) * 16;
            so  = ((size_t)(k0 + r) * ldA) * 2 + c;
            dst = sb + r * RS_T + c;
        } else {
            int r = i >> 2, c = (i & 3) * 16;
            so  = ((size_t)r * ldA + k0) * 2 + c;
            dst = sb + r * RS + c;
        }
        cp16(dst, Ahi + so);
        if (TERMS == 3) cp16(dst + Lay<TERMS>::ALO, Alo + so);
    }
#pragma unroll
    for (int p = 0; p < 2; ++p) {
        int i = p * 256 + tid;
        int r = i >> 2, c = (i & 3) * 16;
        size_t so = ((size_t)r * ldB + k0) * 2 + c;
        uint32_t dst = sb + Lay<TERMS>::BHI + r * RS + c;
        cp16(dst, Bhi + so);
        if (TERMS >= 2) cp16(dst + (Lay<TERMS>::BLO - Lay<TERMS>::BHI), Blo + so);
    }
}

// ===========================================================================
// Generic split-fp16 GEMM (proj/scores) — UNCHANGED from the R12 champion.
// ===========================================================================
template <int TRANSA, int BIAS, int TERMS, int OUTSPLIT, int BALLAST>
__global__ void __launch_bounds__(256)
mma3s_kernel(const __half* __restrict__ Ahi_, const __half* __restrict__ Alo_,
             const __half* __restrict__ Bhi_, const __half* __restrict__ Blo_,
             const float* __restrict__ bias, float* __restrict__ Cf,
             __half* __restrict__ Chi, __half* __restrict__ Clo,
             const float4* __restrict__ bsrc, void* __restrict__ bdst,
             int K, int ldA, int ldB, int ldC,
             unsigned long long sA, unsigned long long sB, unsigned long long sC) {
    constexpr int ALOo = Lay<TERMS>::ALO;
    constexpr int BHIo = Lay<TERMS>::BHI;
    constexpr int BLOo = Lay<TERMS>::BLO;
    constexpr int STG  = Lay<TERMS>::STG;
    constexpr int BUPT  = (BALLAST == 1) ? 128 : 0;
    constexpr int BNBAL = (BALLAST == 1) ? 2   : 0;

    extern __shared__ __align__(128) char sm[];
    const uint32_t sbase = smem_u32(sm);
    const int tid = threadIdx.x, lane = tid & 31, wid = tid >> 5;
    const int wm = (wid & 1) * 64, wn = (wid >> 1) * 32;
    const int m0 = blockIdx.y * 128, n0 = blockIdx.x * 128, b = blockIdx.z;
    const int ctaId = blockIdx.x + gridDim.x * (blockIdx.y + gridDim.y * blockIdx.z);

    const size_t aOff = TRANSA ? ((size_t)b * sA + m0) * 2
                               : ((size_t)b * sA + (size_t)m0 * ldA) * 2;
    const char* Ahi = reinterpret_cast<const char*>(Ahi_) + aOff;
    const char* Alo = (TERMS == 3) ? reinterpret_cast<const char*>(Alo_) + aOff : nullptr;
    const size_t bOff = ((size_t)b * sB + (size_t)n0 * ldB) * 2;
    const char* Bhi = reinterpret_cast<const char*>(Bhi_) + bOff;
    const char* Blo = (TERMS >= 2) ? reinterpret_cast<const char*>(Blo_) + bOff : nullptr;

    float* biasS = reinterpret_cast<float*>(sm + 2 * STG);
    if (BIAS && tid < 128) biasS[tid] = bias[n0 + tid];

    float acc[4][4][4];
#pragma unroll
    for (int i = 0; i < 4; ++i)
#pragma unroll
        for (int j = 0; j < 4; ++j)
#pragma unroll
            for (int v = 0; v < 4; ++v) acc[i][j][v] = 0.0f;

    const int aM_row = lane & 15;
    const int aM_col = (lane & 16) ? 8 : 0;
    const int aT_k   = (lane & 7) + ((lane & 16) ? 8 : 0);
    const int aT_m   = (lane & 8) ? 8 : 0;
    const int bN_row = (lane & 7) + ((lane & 16) ? 8 : 0);
    const int bN_col = (lane & 8) ? 8 : 0;

    const int nIter = K >> 5;
    issue_stage<TRANSA, TERMS>(sbase, Ahi, Alo, Bhi, Blo, 0, ldA, ldB, tid);
    CP_COMMIT();

    for (int ch = 0; ch < nIter; ++ch) {
        float4 bv[BNBAL ? BNBAL : 1];
        size_t bu[BNBAL ? BNBAL : 1];
        if (BALLAST) {
#pragma unroll
            for (int t = 0; t < BNBAL; ++t) {
                int idx = ch * BNBAL + t;
                if (idx < BUPT) {
                    bu[t] = ((size_t)ctaId * BUPT + idx) * 256 + tid;
                    bv[t] = __ldg(bsrc + bu[t]);
                } else {
                    bu[t] = (size_t)-1;
                }
            }
        }

        if (ch + 1 < nIter) {
            issue_stage<TRANSA, TERMS>(sbase + ((ch + 1) & 1) * STG, Ahi, Alo, Bhi, Blo,
                                       (ch + 1) * 32, ldA, ldB, tid);
            CP_COMMIT();
            asm volatile("cp.async.wait_group 1;" ::: "memory");
        } else {
            asm volatile("cp.async.wait_group 0;" ::: "memory");
        }
        __syncthreads();

        const uint32_t sb = sbase + (ch & 1) * STG;
#pragma unroll
        for (int ks = 0; ks < 2; ++ks) {
            uint32_t Ah[4][4], Al[4][4], Bh[2][4], Bl[2][4];
#pragma unroll
            for (int j = 0; j < 2; ++j) {
                uint32_t o = (uint32_t)(wn + j * 16 + bN_row) * RS +
                             (uint32_t)(ks * 16 + bN_col) * 2;
                ldsm4(Bh[j], sb + BHIo + o);
                if (TERMS >= 2) ldsm4(Bl[j], sb + BLOo + o);
            }
#pragma unroll
            for (int mi = 0; mi < 4; ++mi) {
                if (TRANSA) {
                    uint32_t o = (uint32_t)(ks * 16 + aT_k) * RS_T +
                                 (uint32_t)(wm + mi * 16 + aT_m) * 2;
                    ldsm4t(Ah[mi], sb + o);
                    if (TERMS == 3) ldsm4t(Al[mi], sb + ALOo + o);
                } else {
                    uint32_t o = (uint32_t)(wm + mi * 16 + aM_row) * RS +
                                 (uint32_t)(ks * 16 + aM_col) * 2;
                    ldsm4(Ah[mi], sb + o);
                    if (TERMS == 3) ldsm4(Al[mi], sb + ALOo + o);
                }
            }
#pragma unroll
            for (int mi = 0; mi < 4; ++mi)
#pragma unroll
                for (int nj = 0; nj < 4; ++nj)
                    mma_f16(acc[mi][nj], Ah[mi],
                            Bh[nj >> 1][(nj & 1) * 2], Bh[nj >> 1][(nj & 1) * 2 + 1]);
            if (TERMS >= 2) {
#pragma unroll
                for (int mi = 0; mi < 4; ++mi)
#pragma unroll
                    for (int nj = 0; nj < 4; ++nj)
                        mma_f16(acc[mi][nj], Ah[mi],
                                Bl[nj >> 1][(nj & 1) * 2], Bl[nj >> 1][(nj & 1) * 2 + 1]);
            }
            if (TERMS == 3) {
#pragma unroll
                for (int mi = 0; mi < 4; ++mi)
#pragma unroll
                    for (int nj = 0; nj < 4; ++nj)
                        mma_f16(acc[mi][nj], Al[mi],
                                Bh[nj >> 1][(nj & 1) * 2], Bh[nj >> 1][(nj & 1) * 2 + 1]);
            }
        }

        if (BALLAST) {
#pragma unroll
            for (int t = 0; t < BNBAL; ++t) {
                if (bu[t] != (size_t)-1) {
                    uint32_t h0 = pack_h2(bv[t].x, bv[t].y);
                    uint32_t h1 = pack_h2(bv[t].z, bv[t].w);
                    reinterpret_cast<uint2*>(bdst)[bu[t]] = make_uint2(h0, h1);
                }
            }
        }
        __syncthreads();
    }

    const int q4 = lane >> 2, t4 = lane & 3;
#pragma unroll
    for (int mi = 0; mi < 4; ++mi) {
#pragma unroll
        for (int nj = 0; nj < 4; ++nj) {
            int r0 = wm + mi * 16 + q4;
            int c0 = wn + nj * 8 + t4 * 2;
            float b0 = BIAS ? biasS[c0] : 0.0f;
            float b1 = BIAS ? biasS[c0 + 1] : 0.0f;
            float v00 = acc[mi][nj][0] + b0, v01 = acc[mi][nj][1] + b1;
            float v10 = acc[mi][nj][2] + b0, v11 = acc[mi][nj][3] + b1;
            if (OUTSPLIT) {
                size_t e0 = (size_t)b * sC + (size_t)(m0 + r0) * ldC + n0 + c0;
                size_t e1 = (size_t)b * sC + (size_t)(m0 + r0 + 8) * ldC + n0 + c0;
                uint32_t h, l;
                split2h(v00, v01, h, l);
                *reinterpret_cast<uint32_t*>(reinterpret_cast<char*>(Chi) + e0 * 2) = h;
                *reinterpret_cast<uint32_t*>(reinterpret_cast<char*>(Clo) + e0 * 2) = l;
                split2h(v10, v11, h, l);
                *reinterpret_cast<uint32_t*>(reinterpret_cast<char*>(Chi) + e1 * 2) = h;
                *reinterpret_cast<uint32_t*>(reinterpret_cast<char*>(Clo) + e1 * 2) = l;
            } else {
                float* Cb = Cf + (size_t)b * sC + (size_t)(m0 + r0) * ldC + n0 + c0;
                *reinterpret_cast<float2*>(Cb) = make_float2(v00, v01);
                *reinterpret_cast<float2*>(Cb + (size_t)8 * ldC) = make_float2(v10, v11);
            }
        }
    }
}

// ===========================================================================
// AV kernel, 64x64 warp tiles: CTA 256(m=c) x 128(n=q), 8 warps (4m x 2n),
// TERMS=1, fp32 accs. Per warp per ks: 8 LDSM.x4 -> 32 HMMA (ratio 4:1).
// Ballast: qf -> concat-first-half copy, 1 float4/thread/chunk.
// 1024 CTAs * 32 chunks * 256 thr = 8.39M float4 = exactly qf's extent.
// ===========================================================================
#define AV_A_BYTES 20480            /* 256 rows * RS */
#define AV_B_BYTES 10240            /* 128 rows * RS */
#define AV_STG     (AV_A_BYTES + AV_B_BYTES)
#define AV_SMEM    (2 * AV_STG + 256)

__global__ void __launch_bounds__(256)
mma_av_kernel(const __half* __restrict__ V_, const __half* __restrict__ P_,
              float* __restrict__ Cf,
              const float4* __restrict__ bsrc, float4* __restrict__ bdst) {
    extern __shared__ __align__(128) char sm[];
    const uint32_t sbase = smem_u32(sm);
    const int tid = threadIdx.x, lane = tid & 31, wid = tid >> 5;
    const int wm = (wid >> 1) * 64;          // 0,64,128,192
    const int wn = (wid & 1) * 64;           // 0,64
    const int m0 = blockIdx.y * 256, n0 = blockIdx.x * 128, b = blockIdx.z;
    const int ctaId = blockIdx.x + gridDim.x * (blockIdx.y + gridDim.y * blockIdx.z);

    const char* Vb = reinterpret_cast<const char*>(V_) +
                     ((size_t)b * CH * HW + (size_t)m0 * HW) * 2;
    const char* Pb = reinterpret_cast<const char*>(P_) +
                     ((size_t)b * HW * HW + (size_t)n0 * HW) * 2;

    float acc[4][8][4];
#pragma unroll
    for (int i = 0; i < 4; ++i)
#pragma unroll
        for (int j = 0; j < 8; ++j)
#pragma unroll
            for (int v = 0; v < 4; ++v) acc[i][j][v] = 0.0f;

    const int aM_row = lane & 15;
    const int aM_col = (lane & 16) ? 8 : 0;
    const int bN_row = (lane & 7) + ((lane & 16) ? 8 : 0);
    const int bN_col = (lane & 8) ? 8 : 0;

    auto issue = [&](uint32_t sb, int k0) {
#pragma unroll
        for (int p = 0; p < 4; ++p) {
            int i = p * 256 + tid;
            int r = i >> 2, c = (i & 3) * 16;
            cp16(sb + r * RS + c, Vb + ((size_t)r * HW + k0) * 2 + c);
        }
#pragma unroll
        for (int p = 0; p < 2; ++p) {
            int i = p * 256 + tid;
            int r = i >> 2, c = (i & 3) * 16;
            cp16(sb + AV_A_BYTES + r * RS + c, Pb + ((size_t)r * HW + k0) * 2 + c);
        }
    };

    const int nIter = HW >> 5;               // 32
    issue(sbase, 0);
    CP_COMMIT();

    for (int ch = 0; ch < nIter; ++ch) {
        // ballast: ONE float4 copy unit per chunk (bounds-exact)
        size_t bu = ((size_t)ctaId * 32 + ch) * 256 + tid;
        float4 bv = __ldg(bsrc + bu);

        if (ch + 1 < nIter) {
            issue(sbase + ((ch + 1) & 1) * AV_STG, (ch + 1) * 32);
            CP_COMMIT();
            asm volatile("cp.async.wait_group 1;" ::: "memory");
        } else {
            asm volatile("cp.async.wait_group 0;" ::: "memory");
        }
        __syncthreads();

        const uint32_t sb = sbase + (ch & 1) * AV_STG;
#pragma unroll
        for (int ks = 0; ks < 2; ++ks) {
            uint32_t Ah[4][4], Bh[4][4];
#pragma unroll
            for (int j = 0; j < 4; ++j) {
                uint32_t o = (uint32_t)(wn + j * 16 + bN_row) * RS +
                             (uint32_t)(ks * 16 + bN_col) * 2;
                ldsm4(Bh[j], sb + AV_A_BYTES + o);
            }
#pragma unroll
            for (int mi = 0; mi < 4; ++mi) {
                uint32_t o = (uint32_t)(wm + mi * 16 + aM_row) * RS +
                             (uint32_t)(ks * 16 + aM_col) * 2;
                ldsm4(Ah[mi], sb + o);
            }
#pragma unroll
            for (int mi = 0; mi < 4; ++mi)
#pragma unroll
                for (int nj = 0; nj < 8; ++nj)
                    mma_f16(acc[mi][nj], Ah[mi],
                            Bh[nj >> 1][(nj & 1) * 2], Bh[nj >> 1][(nj & 1) * 2 + 1]);
        }

        {
            size_t bb = bu >> 19;              // perb = 2^19 float4 per batch
            size_t rr = bu & 524287u;
            bdst[(bb << 20) + rr] = bv;        // out batch stride = 2^20 float4
        }
        __syncthreads();
    }

    const int q4 = lane >> 2, t4 = lane & 3;
    float* Cb = Cf + (size_t)b * (2 * CH * HW) + (size_t)CH * HW;
#pragma unroll
    for (int mi = 0; mi < 4; ++mi) {
#pragma unroll
        for (int nj = 0; nj < 8; ++nj) {
            int r0 = m0 + wm + mi * 16 + q4;
            int c0 = n0 + wn + nj * 8 + t4 * 2;
            *reinterpret_cast<float2*>(Cb + (size_t)r0 * HW + c0) =
                make_float2(acc[mi][nj][0], acc[mi][nj][1]);
            *reinterpret_cast<float2*>(Cb + (size_t)(r0 + 8) * HW + c0) =
                make_float2(acc[mi][nj][2], acc[mi][nj][3]);
        }
    }
}

// ===========================================================================
// Prelude: qf -> XqHi (hi split) and W -> WHi/WLo.
// ===========================================================================
__global__ void prelude_kernel(const float4* __restrict__ qf, uint2* __restrict__ XqHi,
                               const float4* __restrict__ Wm, uint2* __restrict__ WHi,
                               uint2* __restrict__ WLo) {
    int tid = threadIdx.x;
    if (blockIdx.x < 8192) {
#pragma unroll
        for (int i = 0; i < 4; ++i) {
            size_t u = ((size_t)blockIdx.x * 4 + i) * 256 + tid;
            float4 v = qf[u];
            XqHi[u] = make_uint2(pack_h2(v.x, v.y), pack_h2(v.z, v.w));
        }
    } else {
        int b2 = blockIdx.x - 8192;
#pragma unroll
        for (int i = 0; i < 4; ++i) {
            size_t u = ((size_t)b2 * 4 + i) * 256 + tid;
            float4 v = Wm[u];
            uint32_t h0, l0, h1, l1;
            split2h(v.x, v.y, h0, l0);
            split2h(v.z, v.w, h1, l1);
            WHi[u] = make_uint2(h0, h1);
            WLo[u] = make_uint2(l0, l1);
        }
    }
}

// ===========================================================================
// Row softmax over 1024 fp32 scores; writes fp16 probs (hi only)
// ===========================================================================
__global__ void softmax_rows() {
    int row = blockIdx.x;
    const float* r = g_S + (size_t)row * HW;
    int tid = threadIdx.x;
    __shared__ float red[8];

    float4 v = *reinterpret_cast<const float4*>(r + tid * 4);
    float m = fmaxf(fmaxf(v.x, v.y), fmaxf(v.z, v.w));
#pragma unroll
    for (int off = 16; off; off >>= 1) m = fmaxf(m, __shfl_xor_sync(0xffffffffu, m, off));
    if ((tid & 31) == 0) red[tid >> 5] = m;
    __syncthreads();
    float rowmax = red[0];
#pragma unroll
    for (int i = 1; i < 8; ++i) rowmax = fmaxf(rowmax, red[i]);

    v.x = __expf(v.x - rowmax);
    v.y = __expf(v.y - rowmax);
    v.z = __expf(v.z - rowmax);
    v.w = __expf(v.w - rowmax);
    float s = v.x + v.y + v.z + v.w;
#pragma unroll
    for (int off = 16; off; off >>= 1) s += __shfl_xor_sync(0xffffffffu, s, off);
    __syncthreads();
    if ((tid & 31) == 0) red[tid >> 5] = s;
    __syncthreads();
    float tot = red[0];
#pragma unroll
    for (int i = 1; i < 8; ++i) tot += red[i];
    float inv = 1.0f / tot;

    uint32_t h0 = pack_h2(v.x * inv, v.y * inv);
    uint32_t h1 = pack_h2(v.z * inv, v.w * inv);
    size_t e = (size_t)row * HW + tid * 4;
    *reinterpret_cast<uint2*>(reinterpret_cast<char*>(g_PHi) + e * 2) = make_uint2(h0, h1);
}

// ===========================================================================
extern "C" void kernel_launch(void* const* d_in, const int* in_sizes, int n_in,
                              void* d_out, int out_size) {
    const float* qf   = (const float*)d_in[0];
    const float* pf   = (const float*)d_in[1];
    const float* Wm   = (const float*)d_in[2];
    const float* bias = (const float*)d_in[3];
    float* out = (float*)d_out;

    const int SMEM2 = 2 * Lay<2>::STG + 512;
    const int SMEM3 = 2 * Lay<3>::STG + 512;
    cudaFuncSetAttribute(mma3s_kernel<1,1,2,1,1>, cudaFuncAttributeMaxDynamicSharedMemorySize, SMEM2);
    cudaFuncSetAttribute(mma3s_kernel<1,1,2,1,0>, cudaFuncAttributeMaxDynamicSharedMemorySize, SMEM2);
    cudaFuncSetAttribute(mma3s_kernel<0,0,3,0,0>, cudaFuncAttributeMaxDynamicSharedMemorySize, SMEM3);
    cudaFuncSetAttribute(mma_av_kernel, cudaFuncAttributeMaxDynamicSharedMemorySize, AV_SMEM);

    __half *XqHi, *XpHi, *WHi, *WLo;
    __half *QHi, *QLo, *KHi, *KLo, *PHi;
    float* S;
    cudaGetSymbolAddress((void**)&XqHi, g_XqHi);
    cudaGetSymbolAddress((void**)&XpHi, g_XpHi);
    cudaGetSymbolAddress((void**)&WHi,  g_WHi);  cudaGetSymbolAddress((void**)&WLo,  g_WLo);
    cudaGetSymbolAddress((void**)&QHi,  g_QHi);  cudaGetSymbolAddress((void**)&QLo,  g_QLo);
    cudaGetSymbolAddress((void**)&KHi,  g_KHi);  cudaGetSymbolAddress((void**)&KLo,  g_KLo);
    cudaGetSymbolAddress((void**)&PHi,  g_PHi);
    cudaGetSymbolAddress((void**)&S,    g_S);

    // Prelude: qf split + W split
    prelude_kernel<<<8320, 256>>>((const float4*)qf, (uint2*)XqHi,
                                  (const float4*)Wm, (uint2*)WHi, (uint2*)WLo);

    // proj-q (2-term) + ballast: pf -> XpHi split
    dim3 gqk(HID / 128, HW / 128, BATCH);
    mma3s_kernel<1,1,2,1,1><<<gqk, 256, SMEM2>>>(XqHi, nullptr, WHi, WLo, bias,
        nullptr, QHi, QLo, (const float4*)pf, (void*)XpHi, CH, HW, CH, HID,
        (unsigned long long)CH * HW, 0ULL, (unsigned long long)HW * HID);

    // proj-k (2-term), clean
    mma3s_kernel<1,1,2,1,0><<<gqk, 256, SMEM2>>>(XpHi, nullptr, WHi, WLo, bias,
        nullptr, KHi, KLo, nullptr, nullptr, CH, HW, CH, HID,
        (unsigned long long)CH * HW, 0ULL, (unsigned long long)HW * HID);

    // Scores (3-term, fp32 out)
    dim3 gs(HW / 128, HW / 128, BATCH);
    mma3s_kernel<0,0,3,0,0><<<gs, 256, SMEM3>>>(QHi, QLo, KHi, KLo, nullptr,
        S, nullptr, nullptr, nullptr, nullptr, HID, HID, HID, HW,
        (unsigned long long)HW * HID, (unsigned long long)HW * HID,
        (unsigned long long)HW * HW);

    softmax_rows<<<BATCH * HW, 256>>>();

    // AV 64x64-warp-tile kernel + qf->out copy ballast
    dim3 gav(HW / 128, CH / 256, BATCH);       // (8, 8, 16) = 1024 CTAs
    mma_av_kernel<<<gav, 256, AV_SMEM>>>(XpHi, PHi, out,
                                         (const float4*)qf, (float4*)out);
}

// round 17
// speedup vs baseline: 1.0962x; 1.0962x over previous
#include <cuda_runtime.h>
#include <cuda_fp16.h>
#include <cstdint>

#define BATCH 16
#define CH    2048
#define HID   256
#define HW    1024

// ---- pre-split fp16 operand storage + fp32 scores ----
__device__ __align__(128) __half g_XqHi[BATCH*CH*HW];
__device__ __align__(128) __half g_XpHi[BATCH*CH*HW];
__device__ __align__(128) __half g_WHi [HID*CH],      g_WLo [HID*CH];
__device__ __align__(128) __half g_QHi [BATCH*HW*HID], g_QLo[BATCH*HW*HID];
__device__ __align__(128) __half g_KHi [BATCH*HW*HID], g_KLo[BATCH*HW*HID];
__device__ __align__(128) __half g_PHi [BATCH*HW*HW];
__device__ __align__(128) float  g_S   [BATCH*HW*HW];

// ===========================================================================
// Helpers (base-target sm_80+ instructions only)
// ===========================================================================
__device__ __forceinline__ uint32_t smem_u32(const void* p) {
    uint32_t a;
    asm("{ .reg .u64 t; cvta.to.shared.u64 t, %1; cvt.u32.u64 %0, t; }" : "=r"(a) : "l"(p));
    return a;
}
__device__ __forceinline__ void ldsm4(uint32_t (&r)[4], uint32_t addr) {
    asm volatile("ldmatrix.sync.aligned.m8n8.x4.shared.b16 {%0,%1,%2,%3}, [%4];"
                 : "=r"(r[0]), "=r"(r[1]), "=r"(r[2]), "=r"(r[3]) : "r"(addr));
}
__device__ __forceinline__ void ldsm4t(uint32_t (&r)[4], uint32_t addr) {
    asm volatile("ldmatrix.sync.aligned.m8n8.x4.trans.shared.b16 {%0,%1,%2,%3}, [%4];"
                 : "=r"(r[0]), "=r"(r[1]), "=r"(r[2]), "=r"(r[3]) : "r"(addr));
}
__device__ __forceinline__ void mma_f16(float (&d)[4], const uint32_t (&a)[4],
                                        uint32_t b0, uint32_t b1) {
    asm volatile("mma.sync.aligned.m16n8k16.row.col.f32.f16.f16.f32 "
                 "{%0,%1,%2,%3}, {%4,%5,%6,%7}, {%8,%9}, {%0,%1,%2,%3};"
                 : "+f"(d[0]), "+f"(d[1]), "+f"(d[2]), "+f"(d[3])
                 : "r"(a[0]), "r"(a[1]), "r"(a[2]), "r"(a[3]), "r"(b0), "r"(b1));
}
__device__ __forceinline__ void split2h(float x0, float x1, uint32_t& hi, uint32_t& lo) {
    uint32_t h;
    asm("cvt.rn.f16x2.f32 %0, %1, %2;" : "=r"(h) : "f"(x1), "f"(x0));
    __half2 hh = *reinterpret_cast<__half2*>(&h);
    float h0 = __low2float(hh), h1 = __high2float(hh);
    float l0 = x0 - h0, l1 = x1 - h1;
    uint32_t l;
    asm("cvt.rn.f16x2.f32 %0, %1, %2;" : "=r"(l) : "f"(l1), "f"(l0));
    hi = h; lo = l;
}
__device__ __forceinline__ uint32_t pack_h2(float x0, float x1) {
    uint32_t h;
    asm("cvt.rn.f16x2.f32 %0, %1, %2;" : "=r"(h) : "f"(x1), "f"(x0));
    return h;
}
__device__ __forceinline__ void cp16(uint32_t dst, const void* src) {
    asm volatile("cp.async.cg.shared.global [%0], [%1], 16;" :: "r"(dst), "l"(src));
}
#define CP_COMMIT()  asm volatile("cp.async.commit_group;" ::: "memory")

// SMEM geometry: 80B rows (32 f16 + 16B pad) and 272B trans rows are
// conflict-free for every ldmatrix phase.
#define RS     80
#define RS_T   272

// Per-TERMS SMEM layout (bytes within a stage)
template<int TERMS> struct Lay {
    static constexpr int ALO = (TERMS == 3) ? 10240 : 0;
    static constexpr int BHI = (TERMS == 3) ? 20480 : 10240;
    static constexpr int BLO = (TERMS == 3) ? 30720 : ((TERMS == 2) ? 20480 : 10240);
    static constexpr int STG = (TERMS == 3) ? 40960 : ((TERMS == 2) ? 30720 : 20480);
};

// ===========================================================================
// cp.async stage issue: A hi (+lo if TERMS==3), B hi (+lo if TERMS>=2)
// ===========================================================================
template<int TRANSA, int TERMS>
__device__ __forceinline__ void issue_stage(uint32_t sb,
        const char* Ahi, const char* Alo, const char* Bhi, const char* Blo,
        int k0, int ldA, int ldB, int tid) {
#pragma unroll
    for (int p = 0; p < 2; ++p) {
        int i = p * 256 + tid;
        uint32_t dst; size_t so;
        if (TRANSA) {
            int r = i >> 4, c = (i & 15) * 16;
            so  = ((size_t)(k0 + r) * ldA) * 2 + c;
            dst = sb + r * RS_T + c;
        } else {
            int r = i >> 2, c = (i & 3) * 16;
            so  = ((size_t)r * ldA + k0) * 2 + c;
            dst = sb + r * RS + c;
        }
        cp16(dst, Ahi + so);
        if (TERMS == 3) cp16(dst + Lay<TERMS>::ALO, Alo + so);
    }
#pragma unroll
    for (int p = 0; p < 2; ++p) {
        int i = p * 256 + tid;
        int r = i >> 2, c = (i & 3) * 16;
        size_t so = ((size_t)r * ldB + k0) * 2 + c;
        uint32_t dst = sb + Lay<TERMS>::BHI + r * RS + c;
        cp16(dst, Bhi + so);
        if (TERMS >= 2) cp16(dst + (Lay<TERMS>::BLO - Lay<TERMS>::BHI), Blo + so);
    }
}

// ===========================================================================
// Split-fp16 GEMM with optional "ballast" (hidden bandwidth work):
//   BALLAST=0: none
//   BALLAST=1: fp32->fp16(hi) split stream  (2 float4/thread/chunk, UPT=128)
//   BALLAST=2: fp32 copy into concat output (1 float4/thread for ch<16, UPT=16)
// GEMM: C[b][m][n] = sum_k A[m][k]*B[n][k] (+bias[n]); term sweeps, fp32 accs.
// R5-proven pipeline: issue(ch+1) -> commit -> wait 1 -> sync -> compute -> sync.
// ===========================================================================
template <int TRANSA, int BIAS, int TERMS, int OUTSPLIT, int BALLAST>
__global__ void __launch_bounds__(256)
mma3s_kernel(const __half* __restrict__ Ahi_, const __half* __restrict__ Alo_,
             const __half* __restrict__ Bhi_, const __half* __restrict__ Blo_,
             const float* __restrict__ bias, float* __restrict__ Cf,
             __half* __restrict__ Chi, __half* __restrict__ Clo,
             const float4* __restrict__ bsrc, void* __restrict__ bdst,
             int K, int ldA, int ldB, int ldC,
             unsigned long long sA, unsigned long long sB, unsigned long long sC) {
    constexpr int ALOo = Lay<TERMS>::ALO;
    constexpr int BHIo = Lay<TERMS>::BHI;
    constexpr int BLOo = Lay<TERMS>::BLO;
    constexpr int STG  = Lay<TERMS>::STG;
    constexpr int BUPT  = (BALLAST == 1) ? 128 : ((BALLAST == 2) ? 16 : 0);
    constexpr int BNBAL = (BALLAST == 1) ? 2   : ((BALLAST == 2) ? 1  : 0);

    extern __shared__ __align__(128) char sm[];
    const uint32_t sbase = smem_u32(sm);
    const int tid = threadIdx.x, lane = tid & 31, wid = tid >> 5;
    const int wm = (wid & 1) * 64, wn = (wid >> 1) * 32;
    const int m0 = blockIdx.y * 128, n0 = blockIdx.x * 128, b = blockIdx.z;
    const int ctaId = blockIdx.x + gridDim.x * (blockIdx.y + gridDim.y * blockIdx.z);

    const size_t aOff = TRANSA ? ((size_t)b * sA + m0) * 2
                               : ((size_t)b * sA + (size_t)m0 * ldA) * 2;
    const char* Ahi = reinterpret_cast<const char*>(Ahi_) + aOff;
    const char* Alo = (TERMS == 3) ? reinterpret_cast<const char*>(Alo_) + aOff : nullptr;
    const size_t bOff = ((size_t)b * sB + (size_t)n0 * ldB) * 2;
    const char* Bhi = reinterpret_cast<const char*>(Bhi_) + bOff;
    const char* Blo = (TERMS >= 2) ? reinterpret_cast<const char*>(Blo_) + bOff : nullptr;

    float* biasS = reinterpret_cast<float*>(sm + 2 * STG);
    if (BIAS && tid < 128) biasS[tid] = bias[n0 + tid];

    float acc[4][4][4];
#pragma unroll
    for (int i = 0; i < 4; ++i)
#pragma unroll
        for (int j = 0; j < 4; ++j)
#pragma unroll
            for (int v = 0; v < 4; ++v) acc[i][j][v] = 0.0f;

    const int aM_row = lane & 15;
    const int aM_col = (lane & 16) ? 8 : 0;
    const int aT_k   = (lane & 7) + ((lane & 16) ? 8 : 0);
    const int aT_m   = (lane & 8) ? 8 : 0;
    const int bN_row = (lane & 7) + ((lane & 16) ? 8 : 0);
    const int bN_col = (lane & 8) ? 8 : 0;

    const int nIter = K >> 5;
    issue_stage<TRANSA, TERMS>(sbase, Ahi, Alo, Bhi, Blo, 0, ldA, ldB, tid);
    CP_COMMIT();

    for (int ch = 0; ch < nIter; ++ch) {
        float4 bv[BNBAL ? BNBAL : 1];
        size_t bu[BNBAL ? BNBAL : 1];
        if (BALLAST) {
#pragma unroll
            for (int t = 0; t < BNBAL; ++t) {
                int idx = ch * BNBAL + t;
                if (idx < BUPT) {
                    bu[t] = ((size_t)ctaId * BUPT + idx) * 256 + tid;
                    bv[t] = __ldg(bsrc + bu[t]);
                } else {
                    bu[t] = (size_t)-1;
                }
            }
        }

        if (ch + 1 < nIter) {
            issue_stage<TRANSA, TERMS>(sbase + ((ch + 1) & 1) * STG, Ahi, Alo, Bhi, Blo,
                                       (ch + 1) * 32, ldA, ldB, tid);
            CP_COMMIT();
            asm volatile("cp.async.wait_group 1;" ::: "memory");
        } else {
            asm volatile("cp.async.wait_group 0;" ::: "memory");
        }
        __syncthreads();

        const uint32_t sb = sbase + (ch & 1) * STG;
#pragma unroll
        for (int ks = 0; ks < 2; ++ks) {
            uint32_t Ah[4][4], Al[4][4], Bh[2][4], Bl[2][4];
#pragma unroll
            for (int j = 0; j < 2; ++j) {
                uint32_t o = (uint32_t)(wn + j * 16 + bN_row) * RS +
                             (uint32_t)(ks * 16 + bN_col) * 2;
                ldsm4(Bh[j], sb + BHIo + o);
                if (TERMS >= 2) ldsm4(Bl[j], sb + BLOo + o);
            }
#pragma unroll
            for (int mi = 0; mi < 4; ++mi) {
                if (TRANSA) {
                    uint32_t o = (uint32_t)(ks * 16 + aT_k) * RS_T +
                                 (uint32_t)(wm + mi * 16 + aT_m) * 2;
                    ldsm4t(Ah[mi], sb + o);
                    if (TERMS == 3) ldsm4t(Al[mi], sb + ALOo + o);
                } else {
                    uint32_t o = (uint32_t)(wm + mi * 16 + aM_row) * RS +
                                 (uint32_t)(ks * 16 + aM_col) * 2;
                    ldsm4(Ah[mi], sb + o);
                    if (TERMS == 3) ldsm4(Al[mi], sb + ALOo + o);
                }
            }
#pragma unroll
            for (int mi = 0; mi < 4; ++mi)
#pragma unroll
                for (int nj = 0; nj < 4; ++nj)
                    mma_f16(acc[mi][nj], Ah[mi],
                            Bh[nj >> 1][(nj & 1) * 2], Bh[nj >> 1][(nj & 1) * 2 + 1]);
            if (TERMS >= 2) {
#pragma unroll
                for (int mi = 0; mi < 4; ++mi)
#pragma unroll
                    for (int nj = 0; nj < 4; ++nj)
                        mma_f16(acc[mi][nj], Ah[mi],
                                Bl[nj >> 1][(nj & 1) * 2], Bl[nj >> 1][(nj & 1) * 2 + 1]);
            }
            if (TERMS == 3) {
#pragma unroll
                for (int mi = 0; mi < 4; ++mi)
#pragma unroll
                    for (int nj = 0; nj < 4; ++nj)
                        mma_f16(acc[mi][nj], Al[mi],
                                Bh[nj >> 1][(nj & 1) * 2], Bh[nj >> 1][(nj & 1) * 2 + 1]);
            }
        }

        if (BALLAST) {
#pragma unroll
            for (int t = 0; t < BNBAL; ++t) {
                if (bu[t] != (size_t)-1) {
                    if (BALLAST == 1) {
                        uint32_t h0 = pack_h2(bv[t].x, bv[t].y);
                        uint32_t h1 = pack_h2(bv[t].z, bv[t].w);
                        reinterpret_cast<uint2*>(bdst)[bu[t]] = make_uint2(h0, h1);
                    } else {
                        size_t bb = bu[t] >> 19;            // perb = 2^19 float4/batch
                        size_t rr = bu[t] & 524287u;
                        reinterpret_cast<float4*>(bdst)[(bb << 20) + rr] = bv[t];
                    }
                }
            }
        }
        __syncthreads();
    }

    const int q4 = lane >> 2, t4 = lane & 3;
#pragma unroll
    for (int mi = 0; mi < 4; ++mi) {
#pragma unroll
        for (int nj = 0; nj < 4; ++nj) {
            int r0 = wm + mi * 16 + q4;
            int c0 = wn + nj * 8 + t4 * 2;
            float b0 = BIAS ? biasS[c0] : 0.0f;
            float b1 = BIAS ? biasS[c0 + 1] : 0.0f;
            float v00 = acc[mi][nj][0] + b0, v01 = acc[mi][nj][1] + b1;
            float v10 = acc[mi][nj][2] + b0, v11 = acc[mi][nj][3] + b1;
            if (OUTSPLIT) {
                size_t e0 = (size_t)b * sC + (size_t)(m0 + r0) * ldC + n0 + c0;
                size_t e1 = (size_t)b * sC + (size_t)(m0 + r0 + 8) * ldC + n0 + c0;
                uint32_t h, l;
                split2h(v00, v01, h, l);
                *reinterpret_cast<uint32_t*>(reinterpret_cast<char*>(Chi) + e0 * 2) = h;
                *reinterpret_cast<uint32_t*>(reinterpret_cast<char*>(Clo) + e0 * 2) = l;
                split2h(v10, v11, h, l);
                *reinterpret_cast<uint32_t*>(reinterpret_cast<char*>(Chi) + e1 * 2) = h;
                *reinterpret_cast<uint32_t*>(reinterpret_cast<char*>(Clo) + e1 * 2) = l;
            } else {
                float* Cb = Cf + (size_t)b * sC + (size_t)(m0 + r0) * ldC + n0 + c0;
                *reinterpret_cast<float2*>(Cb) = make_float2(v00, v01);
                *reinterpret_cast<float2*>(Cb + (size_t)8 * ldC) = make_float2(v10, v11);
            }
        }
    }
}

// ===========================================================================
// Prelude: qf -> XqHi (hi split) and W -> WHi/WLo.
// grid 8320 x 256: blocks [0,8192) qf (4 float4 units/thread), [8192,8320) W.
// ===========================================================================
__global__ void prelude_kernel(const float4* __restrict__ qf, uint2* __restrict__ XqHi,
                               const float4* __restrict__ Wm, uint2* __restrict__ WHi,
                               uint2* __restrict__ WLo) {
    int tid = threadIdx.x;
    if (blockIdx.x < 8192) {
#pragma unroll
        for (int i = 0; i < 4; ++i) {
            size_t u = ((size_t)blockIdx.x * 4 + i) * 256 + tid;
            float4 v = qf[u];
            XqHi[u] = make_uint2(pack_h2(v.x, v.y), pack_h2(v.z, v.w));
        }
    } else {
        int b2 = blockIdx.x - 8192;
#pragma unroll
        for (int i = 0; i < 4; ++i) {
            size_t u = ((size_t)b2 * 4 + i) * 256 + tid;
            float4 v = Wm[u];
            uint32_t h0, l0, h1, l1;
            split2h(v.x, v.y, h0, l0);
            split2h(v.z, v.w, h1, l1);
            WHi[u] = make_uint2(h0, h1);
            WLo[u] = make_uint2(l0, l1);
        }
    }
}

// ===========================================================================
// Warp-per-row softmax: 1024 fp32 scores per row, 32 elements per lane,
// zero barriers, zero smem; writes fp16 probs (hi only).
// grid = BATCH*HW/8 blocks of 256 threads (8 warps = 8 rows per block).
// ===========================================================================
__global__ void softmax_rows_warp() {
    const int row  = blockIdx.x * 8 + (threadIdx.x >> 5);
    const int lane = threadIdx.x & 31;
    const float4* r = reinterpret_cast<const float4*>(g_S + (size_t)row * HW);

    float4 v[8];
    float m = -1e30f;
#pragma unroll
    for (int j = 0; j < 8; ++j) {
        v[j] = __ldg(r + lane + 32 * j);
        m = fmaxf(m, fmaxf(fmaxf(v[j].x, v[j].y), fmaxf(v[j].z, v[j].w)));
    }
#pragma unroll
    for (int off = 16; off; off >>= 1) m = fmaxf(m, __shfl_xor_sync(0xffffffffu, m, off));

    float s = 0.0f;
#pragma unroll
    for (int j = 0; j < 8; ++j) {
        v[j].x = __expf(v[j].x - m);
        v[j].y = __expf(v[j].y - m);
        v[j].z = __expf(v[j].z - m);
        v[j].w = __expf(v[j].w - m);
        s += (v[j].x + v[j].y) + (v[j].z + v[j].w);
    }
#pragma unroll
    for (int off = 16; off; off >>= 1) s += __shfl_xor_sync(0xffffffffu, s, off);
    const float inv = 1.0f / s;

    uint2* dst = reinterpret_cast<uint2*>(reinterpret_cast<char*>(g_PHi) +
                                          (size_t)row * HW * 2);
#pragma unroll
    for (int j = 0; j < 8; ++j)
        dst[lane + 32 * j] = make_uint2(pack_h2(v[j].x * inv, v[j].y * inv),
                                        pack_h2(v[j].z * inv, v[j].w * inv));
}

// ===========================================================================
extern "C" void kernel_launch(void* const* d_in, const int* in_sizes, int n_in,
                              void* d_out, int out_size) {
    const float* qf   = (const float*)d_in[0];
    const float* pf   = (const float*)d_in[1];
    const float* Wm   = (const float*)d_in[2];
    const float* bias = (const float*)d_in[3];
    float* out = (float*)d_out;

    const int SMEM2 = 2 * Lay<2>::STG + 512;
    const int SMEM3 = 2 * Lay<3>::STG + 512;
    const int SMEM1 = 2 * Lay<1>::STG + 512;
    cudaFuncSetAttribute(mma3s_kernel<1,1,2,1,1>, cudaFuncAttributeMaxDynamicSharedMemorySize, SMEM2);
    cudaFuncSetAttribute(mma3s_kernel<1,1,2,1,0>, cudaFuncAttributeMaxDynamicSharedMemorySize, SMEM2);
    cudaFuncSetAttribute(mma3s_kernel<0,0,3,0,0>, cudaFuncAttributeMaxDynamicSharedMemorySize, SMEM3);
    cudaFuncSetAttribute(mma3s_kernel<0,0,1,0,2>, cudaFuncAttributeMaxDynamicSharedMemorySize, SMEM1);

    __half *XqHi, *XpHi, *WHi, *WLo;
    __half *QHi, *QLo, *KHi, *KLo, *PHi;
    float* S;
    cudaGetSymbolAddress((void**)&XqHi, g_XqHi);
    cudaGetSymbolAddress((void**)&XpHi, g_XpHi);
    cudaGetSymbolAddress((void**)&WHi,  g_WHi);  cudaGetSymbolAddress((void**)&WLo,  g_WLo);
    cudaGetSymbolAddress((void**)&QHi,  g_QHi);  cudaGetSymbolAddress((void**)&QLo,  g_QLo);
    cudaGetSymbolAddress((void**)&KHi,  g_KHi);  cudaGetSymbolAddress((void**)&KLo,  g_KLo);
    cudaGetSymbolAddress((void**)&PHi,  g_PHi);
    cudaGetSymbolAddress((void**)&S,    g_S);

    // Prelude: qf split + W split (pf split and qf->out copy ride as ballast)
    prelude_kernel<<<8320, 256>>>((const float4*)qf, (uint2*)XqHi,
                                  (const float4*)Wm, (uint2*)WHi, (uint2*)WLo);

    // proj-q (2-term) + ballast: pf -> XpHi split
    dim3 gqk(HID / 128, HW / 128, BATCH);
    mma3s_kernel<1,1,2,1,1><<<gqk, 256, SMEM2>>>(XqHi, nullptr, WHi, WLo, bias,
        nullptr, QHi, QLo, (const float4*)pf, (void*)XpHi, CH, HW, CH, HID,
        (unsigned long long)CH * HW, 0ULL, (unsigned long long)HW * HID);

    // proj-k (2-term), clean — XpHi is complete because proj-q finished first
    mma3s_kernel<1,1,2,1,0><<<gqk, 256, SMEM2>>>(XpHi, nullptr, WHi, WLo, bias,
        nullptr, KHi, KLo, nullptr, nullptr, CH, HW, CH, HID,
        (unsigned long long)CH * HW, 0ULL, (unsigned long long)HW * HID);

    // Scores (3-term, fp32 out)
    dim3 gs(HW / 128, HW / 128, BATCH);
    mma3s_kernel<0,0,3,0,0><<<gs, 256, SMEM3>>>(QHi, QLo, KHi, KLo, nullptr,
        S, nullptr, nullptr, nullptr, nullptr, HID, HID, HID, HW,
        (unsigned long long)HW * HID, (unsigned long long)HW * HID,
        (unsigned long long)HW * HW);

    softmax_rows_warp<<<BATCH * HW / 8, 256>>>();

    // AV (1-term) + ballast: qf -> out concat first half (2048 * 16 * 256 = 8.39M units)
    dim3 gav(HW / 128, CH / 128, BATCH);
    mma3s_kernel<0,0,1,0,2><<<gav, 256, SMEM1>>>(XpHi, nullptr, PHi, nullptr, nullptr,
        out + (size_t)CH * HW, nullptr, nullptr, (const float4*)qf, (void*)out,
        HW, HW, HW, HW,
        (unsigned long long)CH * HW, (unsigned long long)HW * HW,
        (unsigned long long)2 * CH * HW);
}